// round 16
// baseline (speedup 1.0000x reference)
#include <cuda_runtime.h>
#include <cuda_fp16.h>
#include <cstdint>

#define Bb    16
#define T     256
#define NJ    24
#define C     512
#define H     8
#define HD    64
#define BATCH (Bb*NJ)     // 384
#define RTOT  (BATCH*T)   // 98304

// q pre-scale: exp(S*0.125) == exp2(S*0.125*log2(e))
#define QSCALE 0.180336880f

// ---------------- scratch (static device memory; no allocations) ----------------
__device__ uint4 g_xh4[(size_t)RTOT * C / 8];       // LN(x) fp16
__device__ uint4 g_ch4[(size_t)RTOT * C / 8];       // LN(cx) fp16
__device__ uint4 g_wh4[(size_t)3 * C * C / 8];      // W fp16
__device__ uint4 g_qh4[(size_t)RTOT * C / 8];       // q fp16 (pre-scaled)
__device__ uint4 g_kh4[(size_t)RTOT * C / 8];       // k fp16
__device__ uint4 g_vh4[(size_t)RTOT * C / 8];       // v fp16

// ---------------- helpers ----------------
__device__ __forceinline__ uint32_t smem_u32(const void* p) {
    uint32_t a;
    asm("{ .reg .u64 t; cvta.to.shared.u64 t, %1; cvt.u32.u64 %0, t; }" : "=r"(a) : "l"(p));
    return a;
}
__device__ __forceinline__ void cp16(uint32_t dst, const void* src) {
    asm volatile("cp.async.cg.shared.global [%0], [%1], 16;" :: "r"(dst), "l"(src));
}
#define CP_COMMIT() asm volatile("cp.async.commit_group;" ::: "memory")
#define CP_WAIT1()  asm volatile("cp.async.wait_group 1;" ::: "memory")
#define CP_WAIT0()  asm volatile("cp.async.wait_group 0;" ::: "memory")

__device__ __forceinline__ void ldsm_x4(uint32_t* r, uint32_t addr) {
    asm volatile("ldmatrix.sync.aligned.m8n8.x4.shared.b16 {%0,%1,%2,%3}, [%4];"
                 : "=r"(r[0]), "=r"(r[1]), "=r"(r[2]), "=r"(r[3]) : "r"(addr));
}
__device__ __forceinline__ void ldsm_x4_t(uint32_t* r, uint32_t addr) {
    asm volatile("ldmatrix.sync.aligned.m8n8.x4.trans.shared.b16 {%0,%1,%2,%3}, [%4];"
                 : "=r"(r[0]), "=r"(r[1]), "=r"(r[2]), "=r"(r[3]) : "r"(addr));
}
__device__ __forceinline__ void mma16816(float* c, const uint32_t* a,
                                         uint32_t b0, uint32_t b1) {
    asm volatile("mma.sync.aligned.m16n8k16.row.col.f32.f16.f16.f32 "
                 "{%0,%1,%2,%3}, {%4,%5,%6,%7}, {%8,%9}, {%0,%1,%2,%3};"
                 : "+f"(c[0]), "+f"(c[1]), "+f"(c[2]), "+f"(c[3])
                 : "r"(a[0]), "r"(a[1]), "r"(a[2]), "r"(a[3]), "r"(b0), "r"(b1));
}
__device__ __forceinline__ uint32_t pack_hi(float f0, float f1) {
    __half2 hp(__float2half_rn(f0), __float2half_rn(f1));
    return *reinterpret_cast<uint32_t*>(&hp);
}

// ---------------- kernel 1: LN stats + apply + fp16 pack ----------------
__global__ void ln_pack_kernel(const float* __restrict__ x, const float* __restrict__ cx,
                               const float* __restrict__ gamma, const float* __restrict__ beta) {
    int warp = threadIdx.x >> 5, lane = threadIdx.x & 31;
    int row = blockIdx.x * 8 + warp;
    const float* src = (row < RTOT) ? x : cx;
    int r  = (row < RTOT) ? row : row - RTOT;
    int bidx = r >> 8;
    int t    = r & 255;
    int bb = bidx / NJ, n = bidx % NJ;
    const float4* p = (const float4*)(src + ((size_t)(bb * T + t) * NJ + n) * C);
    float4 v[4];
    float s = 0.f, sq = 0.f;
#pragma unroll
    for (int i = 0; i < 4; i++) {
        v[i] = p[lane + 32 * i];
        s  += v[i].x + v[i].y + v[i].z + v[i].w;
        sq += v[i].x * v[i].x + v[i].y * v[i].y + v[i].z * v[i].z + v[i].w * v[i].w;
    }
#pragma unroll
    for (int o = 16; o; o >>= 1) {
        s  += __shfl_xor_sync(0xffffffffu, s, o);
        sq += __shfl_xor_sync(0xffffffffu, sq, o);
    }
    float mu = s * (1.0f / C);
    float rs = rsqrtf(sq * (1.0f / C) - mu * mu + 1e-5f);

    __half* dh = (row < RTOT) ? (__half*)g_xh4 : (__half*)g_ch4;
    size_t rb = (size_t)r * C;
#pragma unroll
    for (int i = 0; i < 4; i++) {
        int e = (lane + 32 * i) * 4;
        float4 g  = *(const float4*)(gamma + e);
        float4 be = *(const float4*)(beta + e);
        float f0 = (v[i].x - mu) * rs * g.x + be.x;
        float f1 = (v[i].y - mu) * rs * g.y + be.y;
        float f2 = (v[i].z - mu) * rs * g.z + be.z;
        float f3 = (v[i].w - mu) * rs * g.w + be.w;
        *(uint2*)(dh + rb + e) = make_uint2(pack_hi(f0, f1), pack_hi(f2, f3));
    }
}

// ---------------- kernel 2: pack weights fp16 ----------------
__global__ void pack_w_kernel(const float* __restrict__ Wq, const float* __restrict__ Wk,
                              const float* __restrict__ Wv) {
    size_t e = ((size_t)blockIdx.x * 256 + threadIdx.x) * 4;
    int z = (int)(e / ((size_t)C * C));
    size_t rem = e % ((size_t)C * C);
    const float* W = (z == 0) ? Wq : (z == 1) ? Wk : Wv;
    float4 w = *(const float4*)(W + rem);
    *(uint2*)((__half*)g_wh4 + e) = make_uint2(pack_hi(w.x, w.y), pack_hi(w.z, w.w));
}

// ---------------- kernel 3: QKV GEMM, fp16, BM=128/BN=256/BK=64, 512 thr, 3-stage ----
// 16 warps = 4(M) x 4(N), warp tile 32x64; acc 64 f32/thread.
// stage = 48KB: A[16K] B[32K]; 3 stages = 144KB; occ-1 (= 4 warps/SMSP).
// rows 128B (8 x 16B chunks), swizzle chunk ^ (row&7).
#define QSTG 49152

__device__ __forceinline__ void qfill(uint32_t s, int k0,
    const __half* Ah_g, const __half* Bh_g, int r0, int o0, int tid) {
#pragma unroll
    for (int j = 0; j < 2; ++j) {   // A: 128 rows x 8 chunks = 1024
        int idx = j * 512 + tid;
        int row = idx >> 3, c = idx & 7;
        uint32_t doff = (uint32_t)(row * 128 + ((c ^ (row & 7)) << 4));
        cp16(s + doff, Ah_g + (size_t)(r0 + row) * C + k0 + c * 8);
    }
#pragma unroll
    for (int j = 0; j < 4; ++j) {   // B: 256 rows x 8 chunks = 2048
        int idx = j * 512 + tid;
        int row = idx >> 3, c = idx & 7;
        uint32_t doff = (uint32_t)(row * 128 + ((c ^ (row & 7)) << 4));
        cp16(s + 16384 + doff, Bh_g + (size_t)(o0 + row) * C + k0 + c * 8);
    }
}

__global__ __launch_bounds__(512, 1) void qkv_gemm_mma() {
    extern __shared__ char sm[];
    uint32_t sb = smem_u32(sm);
    int tid = threadIdx.x;
    int wid = tid >> 5, lane = tid & 31;
    int wm = wid & 3, wn = wid >> 2;          // 4(M) x 4(N) warps, warp tile 32x64

    int z = blockIdx.z;
    const __half* Ah_g = (z == 0) ? (const __half*)g_xh4 : (const __half*)g_ch4;
    const __half* Bh_g = (const __half*)g_wh4 + (size_t)z * C * C;
    __half* dst = (z == 0) ? (__half*)g_qh4 : (z == 1) ? (__half*)g_kh4 : (__half*)g_vh4;

    int r0 = blockIdx.y * 128;
    int o0 = blockIdx.x * 256;

    float acc[2][8][4];
#pragma unroll
    for (int i = 0; i < 2; i++)
#pragma unroll
        for (int j = 0; j < 8; j++)
#pragma unroll
            for (int q = 0; q < 4; q++) acc[i][j][q] = 0.f;

    int a_row   = wm * 32 + (lane & 15);
    int a_khalf = lane >> 4;
    int b_nrow  = wn * 64 + (lane & 7) + ((lane >> 4) << 3);
    int b_khalf = (lane >> 3) & 1;

    qfill(sb,        0,  Ah_g, Bh_g, r0, o0, tid); CP_COMMIT();
    qfill(sb + QSTG, 64, Ah_g, Bh_g, r0, o0, tid); CP_COMMIT();

    for (int c = 0; c < 8; ++c) {        // 8 chunks of BK=64
        if (c < 7) CP_WAIT1(); else CP_WAIT0();
        __syncthreads();
        if (c + 2 < 8) {
            qfill(sb + ((c + 2) % 3) * QSTG, (c + 2) * 64, Ah_g, Bh_g, r0, o0, tid);
            CP_COMMIT();
        }

        uint32_t base = sb + (c % 3) * QSTG;
#pragma unroll
        for (int ks = 0; ks < 4; ++ks) {  // 4 x k16 inside BK=64
            uint32_t ah[2][4];
#pragma unroll
            for (int mt = 0; mt < 2; ++mt) {
                int row = a_row + mt * 16;
                int ch = ks * 2 + a_khalf;
                uint32_t off = (uint32_t)(row * 128 + ((ch ^ (row & 7)) << 4));
                ldsm_x4(ah[mt], base + off);
            }
            uint32_t bh[4][4];
#pragma unroll
            for (int ng = 0; ng < 4; ++ng) {
                int nr = b_nrow + ng * 16;
                int ch = ks * 2 + b_khalf;
                uint32_t off = (uint32_t)(nr * 128 + ((ch ^ (nr & 7)) << 4));
                ldsm_x4(bh[ng], base + 16384 + off);
            }
#pragma unroll
            for (int mt = 0; mt < 2; ++mt)
#pragma unroll
                for (int ng = 0; ng < 4; ++ng)
#pragma unroll
                    for (int hf = 0; hf < 2; ++hf)
                        mma16816(acc[mt][ng * 2 + hf], ah[mt], bh[ng][2 * hf], bh[ng][2 * hf + 1]);
        }
        __syncthreads();
    }

    // ---- epilogue: fp16 store (q gets exp2 pre-scale) ----
    float scale = (z == 0) ? QSCALE : 1.0f;
    int qr = lane >> 2, qc = (lane & 3) * 2;
#pragma unroll
    for (int mt = 0; mt < 2; ++mt) {
        int row = r0 + wm * 32 + mt * 16 + qr;
#pragma unroll
        for (int nt = 0; nt < 8; ++nt) {
            int col = o0 + wn * 64 + nt * 8 + qc;
            float* cc = acc[mt][nt];
            *(uint32_t*)(dst + (size_t)row * C + col)       = pack_hi(cc[0] * scale, cc[1] * scale);
            *(uint32_t*)(dst + (size_t)(row + 8) * C + col) = pack_hi(cc[2] * scale, cc[3] * scale);
        }
    }
}

// ---------------- kernel 4: attention, 128 q/CTA, FULLY-RESIDENT KV, occ-2 ----
// block = (bi, h, th); warp w owns queries [th*128 + 16w, +16).
// smem: Q[16K]@0, K[32K]@16K, V[32K]@48K = 80KB. No mainloop barriers.
#define AQ   0
#define AK   16384
#define AV   49152
#define ATT_SMEM 81920

__global__ __launch_bounds__(256, 2) void attn_mma(const float* __restrict__ x,
                                                   float* __restrict__ out) {
    extern __shared__ char sm[];
    uint32_t sb = smem_u32(sm);
    int tid = threadIdx.x;
    int wid = tid >> 5, lane = tid & 31;

    int th = blockIdx.x & 1;
    int bh = blockIdx.x >> 1;
    int bi = bh / H;
    int h  = bh % H;
    size_t rbase = (size_t)bi * T;
    int q0 = th * 128;

    const __half* qh_g = (const __half*)g_qh4;
    const __half* kh_g = (const __half*)g_kh4;
    const __half* vh_g = (const __half*)g_vh4;

    // Q: 128 rows x 8 chunks
#pragma unroll
    for (int j = 0; j < 4; ++j) {
        int i = j * 256 + tid;
        int r = i >> 3, c = i & 7;
        uint32_t off = (uint32_t)(AQ + r * 128 + ((c ^ (r & 7)) << 4));
        cp16(sb + off, qh_g + (rbase + q0 + r) * C + h * HD + c * 8);
    }
    // K, V: 256 rows x 8 chunks each
#pragma unroll
    for (int j = 0; j < 8; ++j) {
        int i = j * 256 + tid;
        int r = i >> 3, c = i & 7;
        uint32_t off = (uint32_t)(r * 128 + ((c ^ (r & 7)) << 4));
        size_t ga = (rbase + r) * C + h * HD + c * 8;
        cp16(sb + AK + off, kh_g + ga);
        cp16(sb + AV + off, vh_g + ga);
    }
    CP_COMMIT();
    CP_WAIT0();
    __syncthreads();          // the ONLY barrier

    float yacc[8][4];
#pragma unroll
    for (int j = 0; j < 8; j++)
#pragma unroll
        for (int q = 0; q < 4; q++) yacc[j][q] = 0.f;
    float rs[2] = {0.f, 0.f};

    int a_row = wid * 16 + (lane & 15);
    int a_kh  = lane >> 4;
    int b_kr  = (lane & 7) + ((lane >> 4) << 3);
    int b_kh2 = (lane >> 3) & 1;
    int v_kr  = (lane & 7) + (((lane >> 3) & 1) << 3);
    int v_ch  = lane >> 4;

#pragma unroll 1
    for (int nb = 0; nb < 4; ++nb) {
        float sacc[8][4];
#pragma unroll
        for (int j = 0; j < 8; j++)
#pragma unroll
            for (int q = 0; q < 4; q++) sacc[j][q] = 0.f;

        // ---- S' = (q*QSCALE) K^T (4 k16 steps over hd) ----
#pragma unroll
        for (int kt = 0; kt < 4; ++kt) {
            uint32_t ah[4];
            {
                int ch = kt * 2 + a_kh;
                uint32_t off = (uint32_t)(AQ + a_row * 128 + ((ch ^ (a_row & 7)) << 4));
                ldsm_x4(ah, sb + off);
            }
            uint32_t kbh[4][4];
#pragma unroll
            for (int ng = 0; ng < 4; ++ng) {
                int kr = nb * 64 + ng * 16 + b_kr;
                int ch = kt * 2 + b_kh2;
                uint32_t off = (uint32_t)(AK + kr * 128 + ((ch ^ (kr & 7)) << 4));
                ldsm_x4(kbh[ng], sb + off);
            }
#pragma unroll
            for (int ng = 0; ng < 4; ++ng)
#pragma unroll
                for (int hf = 0; hf < 2; ++hf)
                    mma16816(sacc[ng * 2 + hf], ah, kbh[ng][2 * hf], kbh[ng][2 * hf + 1]);
        }

        // ---- E = exp2(S') ; row sums ----
#pragma unroll
        for (int nt = 0; nt < 8; ++nt) {
            float* cc = sacc[nt];
            cc[0] = exp2f(cc[0]);
            cc[1] = exp2f(cc[1]);
            cc[2] = exp2f(cc[2]);
            cc[3] = exp2f(cc[3]);
            rs[0] += cc[0] + cc[1];
            rs[1] += cc[2] + cc[3];
        }

        // ---- Y += P V ----
#pragma unroll
        for (int j = 0; j < 4; ++j) {
            uint32_t pah[4];
            pah[0] = pack_hi(sacc[2 * j][0],     sacc[2 * j][1]);
            pah[1] = pack_hi(sacc[2 * j][2],     sacc[2 * j][3]);
            pah[2] = pack_hi(sacc[2 * j + 1][0], sacc[2 * j + 1][1]);
            pah[3] = pack_hi(sacc[2 * j + 1][2], sacc[2 * j + 1][3]);
            uint32_t vbh[4][4];
#pragma unroll
            for (int hdt = 0; hdt < 4; ++hdt) {
                int vr = nb * 64 + j * 16 + v_kr;
                int ch = hdt * 2 + v_ch;
                uint32_t off = (uint32_t)(AV + vr * 128 + ((ch ^ (vr & 7)) << 4));
                ldsm_x4_t(vbh[hdt], sb + off);
            }
#pragma unroll
            for (int hdt = 0; hdt < 4; ++hdt)
#pragma unroll
                for (int hf = 0; hf < 2; ++hf)
                    mma16816(yacc[hdt * 2 + hf], pah, vbh[hdt][2 * hf], vbh[hdt][2 * hf + 1]);
        }
    }

    // ---- row-sum reduce within quads, normalize, residual add, store ----
#pragma unroll
    for (int i = 0; i < 2; ++i) {
        rs[i] += __shfl_xor_sync(0xffffffffu, rs[i], 1);
        rs[i] += __shfl_xor_sync(0xffffffffu, rs[i], 2);
    }

    int qr = lane >> 2, qc = (lane & 3) * 2;
    int bb = bi / NJ, n = bi % NJ;
    float inv0 = 1.0f / rs[0];
    float inv1 = 1.0f / rs[1];
    int t0 = q0 + wid * 16 + qr;
#pragma unroll
    for (int nt = 0; nt < 8; ++nt) {
        int hd = nt * 8 + qc;
        float* cc = yacc[nt];
        size_t a0 = ((size_t)(bb * T + t0) * NJ + n) * C + h * HD + hd;
        size_t a1 = ((size_t)(bb * T + t0 + 8) * NJ + n) * C + h * HD + hd;
        float2 x0 = *(const float2*)(x + a0);
        float2 x1 = *(const float2*)(x + a1);
        *(float2*)(out + a0) = make_float2(x0.x + cc[0] * inv0, x0.y + cc[1] * inv0);
        *(float2*)(out + a1) = make_float2(x1.x + cc[2] * inv1, x1.y + cc[3] * inv1);
    }
}

// ---------------- launch ----------------
extern "C" void kernel_launch(void* const* d_in, const int* in_sizes, int n_in,
                              void* d_out, int out_size) {
    const float* x     = (const float*)d_in[0];
    const float* cx    = (const float*)d_in[1];
    const float* gamma = (const float*)d_in[2];
    const float* beta  = (const float*)d_in[3];
    const float* Wq    = (const float*)d_in[4];
    const float* Wk    = (const float*)d_in[5];
    const float* Wv    = (const float*)d_in[6];
    float* out = (float*)d_out;

    cudaFuncSetAttribute(qkv_gemm_mma, cudaFuncAttributeMaxDynamicSharedMemorySize, 3 * QSTG);
    cudaFuncSetAttribute(attn_mma, cudaFuncAttributeMaxDynamicSharedMemorySize, ATT_SMEM);

    ln_pack_kernel<<<2 * RTOT / 8, 256>>>(x, cx, gamma, beta);
    pack_w_kernel<<<3 * C * C / 1024, 256>>>(Wq, Wk, Wv);

    dim3 gg(C / 256, RTOT / 128, 3);
    qkv_gemm_mma<<<gg, 512, 3 * QSTG>>>();

    attn_mma<<<BATCH * H * 2, 256, ATT_SMEM>>>(x, out);
}